// round 17
// baseline (speedup 1.0000x reference)
#include <cuda_runtime.h>
#include <cuda_bf16.h>
#include <cuda_fp16.h>
#include <math.h>
#include <stdint.h>

// Problem constants
#define BS 512
#define NE 256
#define NQ 64
#define IN_DIM 512
#define EMBED_DIM 512
#define OUT_DIM 512
#define N_HEADS 8
#define HEAD_DIM 64
#define QKV_DIM (3 * EMBED_DIM)

// Arch-feature gate: tcgen05 only exists in arch-specific passes.
#if defined(__CUDA_ARCH__) && (defined(__CUDA_ARCH_FEAT_SM103_ALL) || defined(__CUDA_ARCH_FEAT_SM100_ALL) || defined(__CUDA_ARCH_FEAT_SM101_ALL))
#define HAS_TCGEN05 1
#else
#define HAS_TCGEN05 0
#endif

// ---------------------------------------------------------------------------
// Scratch (device globals). GEMM operands live in TILE-CONTIGUOUS,
// PRE-SWIZZLED (SW128) layout: [M/128 panels][8 K-chunks][16384 bytes], fp16.
// ---------------------------------------------------------------------------
__device__ __half g_Q[(size_t)BS * NQ * EMBED_DIM];
__device__ __half g_KV[(size_t)BS * NE * (2 * EMBED_DIM)];
__device__ __align__(1024) __half g_ent_h[(size_t)BS * NE * IN_DIM];
__device__ __align__(1024) __half g_q_h[(size_t)BS * NQ * IN_DIM];
__device__ __align__(1024) __half g_attn_h[(size_t)BS * NQ * EMBED_DIM];
__device__ __align__(1024) __half g_WinT_h[(size_t)QKV_DIM * IN_DIM];
__device__ __align__(1024) __half g_WoutT_h[(size_t)OUT_DIM * EMBED_DIM];

// ---------------------------------------------------------------------------
// Common helpers
// ---------------------------------------------------------------------------
__device__ __forceinline__ uint32_t smem_u32(const void* p) {
    uint32_t a;
    asm("{ .reg .u64 t; cvta.to.shared.u64 t, %1; cvt.u32.u64 %0, t; }" : "=r"(a) : "l"(p));
    return a;
}
__device__ __forceinline__ void cp16(uint32_t s, const void* g) {
    asm volatile("cp.async.cg.shared.global [%0], [%1], 16;" :: "r"(s), "l"(g) : "memory");
}
__device__ __forceinline__ void ldsm4(uint32_t* r, uint32_t addr) {
    asm volatile("ldmatrix.sync.aligned.m8n8.x4.shared.b16 {%0,%1,%2,%3}, [%4];"
                 : "=r"(r[0]), "=r"(r[1]), "=r"(r[2]), "=r"(r[3]) : "r"(addr));
}
__device__ __forceinline__ void ldsm4t(uint32_t* r, uint32_t addr) {
    asm volatile("ldmatrix.sync.aligned.m8n8.x4.trans.shared.b16 {%0,%1,%2,%3}, [%4];"
                 : "=r"(r[0]), "=r"(r[1]), "=r"(r[2]), "=r"(r[3]) : "r"(addr));
}
__device__ __forceinline__ void mma_fp16(float* d, const uint32_t* a, const uint32_t* b) {
    asm volatile("mma.sync.aligned.m16n8k16.row.col.f32.f16.f16.f32 "
                 "{%0,%1,%2,%3}, {%4,%5,%6,%7}, {%8,%9}, {%0,%1,%2,%3};"
                 : "+f"(d[0]), "+f"(d[1]), "+f"(d[2]), "+f"(d[3])
                 : "r"(a[0]), "r"(a[1]), "r"(a[2]), "r"(a[3]), "r"(b[0]), "r"(b[1]));
}

// fp32[8] -> fp16 packed 16B unit
__device__ __forceinline__ void pack8h(const float* src, uint4& hv) {
    uint32_t* hp = (uint32_t*)&hv;
#pragma unroll
    for (int j = 0; j < 4; ++j) {
        __half2 h2;
        h2.x = __float2half(src[2 * j]);
        h2.y = __float2half(src[2 * j + 1]);
        hp[j] = *(uint32_t*)&h2;
    }
}
// fp32[4] -> fp16 packed 8B unit
__device__ __forceinline__ void pack4h(const float* src, uint2& hv) {
    uint32_t* hp = (uint32_t*)&hv;
#pragma unroll
    for (int j = 0; j < 2; ++j) {
        __half2 h2;
        h2.x = __float2half(src[2 * j]);
        h2.y = __float2half(src[2 * j + 1]);
        hp[j] = *(uint32_t*)&h2;
    }
}

// byte offset of (m, k) in tiled+swizzled layout (k multiple of 8)
__device__ __forceinline__ size_t tiled_off(int m, int k) {
    const int panel = m >> 7, r = m & 127, ch = k >> 6;
    uint32_t off = (uint32_t)(r << 7) + ((k & 63) << 1);
    off = off ^ ((off >> 3) & 0x70);
    return ((size_t)(panel * 8 + ch) << 14) + off;
}

#if HAS_TCGEN05
// ---------------------------------------------------------------------------
// tcgen05 + bulk-async helpers (arch-specific pass only)
// ---------------------------------------------------------------------------
__device__ __forceinline__ uint32_t elect_one_pred() {
    uint32_t p;
    asm volatile("{\n\t.reg .pred p;\n\telect.sync _|p, 0xFFFFFFFF;\n\tselp.b32 %0, 1, 0, p;\n\t}" : "=r"(p));
    return p;
}
#define TCGEN05_ALLOC(sa, n) \
    asm volatile("tcgen05.alloc.cta_group::1.sync.aligned.shared::cta.b32 [%0], %1;" :: "r"((uint32_t)(sa)), "r"((uint32_t)(n)) : "memory")
#define TCGEN05_DEALLOC(t, n) \
    asm volatile("tcgen05.dealloc.cta_group::1.sync.aligned.b32 %0, %1;" :: "r"(t), "r"((uint32_t)(n)))
#define TCGEN05_RELINQ() \
    asm volatile("tcgen05.relinquish_alloc_permit.cta_group::1.sync.aligned;")
#define TCGEN05_COMMIT(mb) \
    asm volatile("tcgen05.commit.cta_group::1.mbarrier::arrive::one.shared::cluster.b64 [%0];" :: "r"((uint32_t)(mb)) : "memory")
#define TCGEN05_FENCE_AFTER() asm volatile("tcgen05.fence::after_thread_sync;" ::: "memory")
#define TCGEN05_FENCE_BEFORE() asm volatile("tcgen05.fence::before_thread_sync;" ::: "memory")
#define TCGEN05_WAIT_LD() asm volatile("tcgen05.wait::ld.sync.aligned;" ::: "memory")
#define MBARRIER_INIT(mb, cnt) \
    asm volatile("mbarrier.init.shared.b64 [%0], %1;" :: "r"((uint32_t)(mb)), "r"((uint32_t)(cnt)) : "memory")
#define MBARRIER_INVAL(mb) \
    asm volatile("mbarrier.inval.shared.b64 [%0];" :: "r"((uint32_t)(mb)) : "memory")
#define MBARRIER_EXPECT_TX(mb, tx) \
    asm volatile("mbarrier.arrive.expect_tx.shared.b64 _, [%0], %1;" :: "r"((uint32_t)(mb)), "r"((uint32_t)(tx)) : "memory")
#define MBARRIER_WAIT_PARITY(mb, par) do {                                           \
    uint32_t _mb = (uint32_t)(mb); uint32_t _p = (uint32_t)(par); uint32_t _d;       \
    asm volatile("{\n\t.reg .pred p;\n\t"                                            \
        "mbarrier.try_wait.parity.acquire.cta.shared::cta.b64 p, [%1], %2;\n\t"      \
        "selp.b32 %0, 1, 0, p;\n\t}" : "=r"(_d) : "r"(_mb), "r"(_p) : "memory");     \
    if (!_d) {                                                                       \
        asm volatile("{\n\t.reg .pred P1;\n\t"                                       \
            "WL_%=:\n\t"                                                             \
            "mbarrier.try_wait.parity.acquire.cta.shared::cta.b64 P1, [%0], %1, 0x989680;\n\t" \
            "@P1 bra.uni WD_%=;\n\t"                                                 \
            "bra.uni WL_%=;\n\t"                                                     \
            "WD_%=:\n\t}" :: "r"(_mb), "r"(_p) : "memory");                          \
    }                                                                                \
} while (0)

__device__ __forceinline__ void cp_bulk(uint32_t dst, const void* src, uint32_t bytes, uint32_t mb) {
    asm volatile("cp.async.bulk.shared::cta.global.mbarrier::complete_tx::bytes [%0], [%1], %2, [%3];"
                 :: "r"(dst), "l"(src), "r"(bytes), "r"(mb) : "memory");
}

#define TCGEN05_LD_32X32B_X32(r, ta) \
    asm volatile( \
        "tcgen05.ld.sync.aligned.32x32b.x32.b32 " \
        "{%0, %1, %2, %3, %4, %5, %6, %7, " \
        " %8, %9, %10, %11, %12, %13, %14, %15, " \
        " %16, %17, %18, %19, %20, %21, %22, %23, " \
        " %24, %25, %26, %27, %28, %29, %30, %31}, [%32];" \
        : "=r"((r)[0]),  "=r"((r)[1]),  "=r"((r)[2]),  "=r"((r)[3]), \
          "=r"((r)[4]),  "=r"((r)[5]),  "=r"((r)[6]),  "=r"((r)[7]), \
          "=r"((r)[8]),  "=r"((r)[9]),  "=r"((r)[10]), "=r"((r)[11]), \
          "=r"((r)[12]), "=r"((r)[13]), "=r"((r)[14]), "=r"((r)[15]), \
          "=r"((r)[16]), "=r"((r)[17]), "=r"((r)[18]), "=r"((r)[19]), \
          "=r"((r)[20]), "=r"((r)[21]), "=r"((r)[22]), "=r"((r)[23]), \
          "=r"((r)[24]), "=r"((r)[25]), "=r"((r)[26]), "=r"((r)[27]), \
          "=r"((r)[28]), "=r"((r)[29]), "=r"((r)[30]), "=r"((r)[31]) \
        : "r"(ta))

static constexpr uint64_t SMEM_DESC_BASE_SW128 =
    (uint64_t(2) << 61) | (uint64_t(1) << 46) | (uint64_t(64) << 32) | (uint64_t(1) << 16);
#define MAKE_SMEM_DESC(ba) (SMEM_DESC_BASE_SW128 | ((uint64_t)((ba) >> 4) & 0x3FFF))

// Proven operand binding: %3 = idesc, %4 = enable, %5 = zero reg.
__device__ __forceinline__ void mma_f16_ss(uint32_t d, uint64_t da, uint64_t db,
                                           uint32_t idesc, bool en) {
    uint32_t e = en ? 1u : 0u;
    asm volatile(
        "{\n\t.reg .pred p;\n\t"
        "setp.ne.u32 p, %4, 0;\n\t"
        "tcgen05.mma.cta_group::1.kind::f16 [%0], %1, %2, %3, {%5, %5, %5, %5}, p;\n\t"
        "}"
        :: "r"(d), "l"(da), "l"(db), "r"(idesc), "r"(e), "r"(0u)
        : "memory");
}
// idesc: f32 accum, FP16 a (0), FP16 b (0), N=128, M=128
static constexpr uint32_t MMA_IDESC =
    (1u << 4) | ((128u / 8) << 17) | ((128u / 16) << 24);
#endif // HAS_TCGEN05

#define GK 512
#define NCHUNKS 8
#define TILE_BYTES 16384

// ---------------------------------------------------------------------------
// fp16 GEMM v2: B-RESIDENT multi-tile. Each CTA keeps its full B panel
// (8 chunks = 128KB) in smem and streams TM_TILES consecutive A m-panels
// through a 3x16KB pipeline. Two TMEM accumulators overlap epilogue(t-1)
// with MMA(t). Grid: (n_panels, m_panels / TM_TILES).
// ---------------------------------------------------------------------------
#define TM_TILES 8
#define B_SMEM_BYTES (8 * TILE_BYTES)          // 131072
#define A_STAGE_BYTES TILE_BYTES
#define A_NSTAGES 3
#define GEMM_DYN_SMEM (B_SMEM_BYTES + A_NSTAGES * A_STAGE_BYTES + 1024)   // 181248

template <bool EPI, bool OUTH>
__global__ void __launch_bounds__(256)
gemm_fp16(const __half* __restrict__ A, const __half* __restrict__ B,
          void* __restrict__ Cv, int ldc,
          const float* __restrict__ bias, const int* __restrict__ post_mask)
{
    extern __shared__ char dyn_smem[];
    const int tid = threadIdx.x;
    const int wid = tid >> 5;
    const int lane = tid & 31;
    const int pn = blockIdx.x;                 // B n-panel
    const int pm0 = blockIdx.y * TM_TILES;     // first A m-panel
    const int n0 = pn << 7;

    const uint32_t sbase = (smem_u32(dyn_smem) + 1023u) & ~1023u;
    const uint32_t aBase = sbase + B_SMEM_BYTES;

    // panel base pointers (used by BOTH code paths)
    const char* pAbase = (const char*)A + (size_t)pm0 * (8 * TILE_BYTES);
    const char* pBbase = (const char*)B + (size_t)pn * (8 * TILE_BYTES);

#if HAS_TCGEN05
    __shared__ uint32_t s_tmem_ptr[2];
    __shared__ __align__(8) uint64_t s_full[A_NSTAGES];
    __shared__ __align__(8) uint64_t s_empty[A_NSTAGES];
    __shared__ __align__(8) uint64_t s_done[2];
    __shared__ __align__(8) uint64_t s_bfull;

    if (wid == 0) {
        TCGEN05_ALLOC(smem_u32(s_tmem_ptr), 256);
        TCGEN05_RELINQ();
    }
    if (tid == 0) {
#pragma unroll
        for (int j = 0; j < A_NSTAGES; ++j) {
            MBARRIER_INIT(smem_u32(&s_full[j]), 1);
            MBARRIER_INIT(smem_u32(&s_empty[j]), 1);
        }
        MBARRIER_INIT(smem_u32(&s_done[0]), 1);
        MBARRIER_INIT(smem_u32(&s_done[1]), 1);
        MBARRIER_INIT(smem_u32(&s_bfull), 1);
    }
    __syncthreads();

    uint32_t tmem_base;
    asm volatile("ld.shared.b32 %0, [%1];" : "=r"(tmem_base) : "r"(smem_u32(s_tmem_ptr)));

    // prologue (elected): B panel + first 3 A chunks
    if (wid == 0 && elect_one_pred()) {
        const uint32_t bf = smem_u32(&s_bfull);
        MBARRIER_EXPECT_TX(bf, B_SMEM_BYTES);
#pragma unroll
        for (int c = 0; c < 8; ++c)
            cp_bulk(sbase + c * TILE_BYTES, pBbase + (size_t)c * TILE_BYTES, TILE_BYTES, bf);
#pragma unroll
        for (int g = 0; g < A_NSTAGES; ++g) {
            const uint32_t fb = smem_u32(&s_full[g]);
            MBARRIER_EXPECT_TX(fb, A_STAGE_BYTES);
            cp_bulk(aBase + g * A_STAGE_BYTES, pAbase + (size_t)g * TILE_BYTES, A_STAGE_BYTES, fb);
        }
    }

    int fph[A_NSTAGES] = {0, 0, 0};
    int eph[A_NSTAGES] = {0, 0, 0};
    int dph[2] = {0, 0};
    int bwaited = 0;
    const int gmax = TM_TILES * NCHUNKS;

    // per-tile epilogue (all 256 threads)
    auto epilogue = [&](int t) {
        const uint32_t D = tmem_base + ((t & 1) << 7);
        const int rsub = (wid & 3) << 5;
        const int colh = (wid >> 2) << 6;
        const int m = ((pm0 + t) << 7) + rsub + lane;
        bool zero = false;
        if (EPI) zero = (post_mask[m] != 0);

#pragma unroll
        for (int half = 0; half < 2; ++half) {
            const int cbase = colh + half * 32;
            uint32_t r[32];
            TCGEN05_LD_32X32B_X32(r, D + cbase);
            TCGEN05_WAIT_LD();
#pragma unroll
            for (int j = 0; j < 32; j += 4) {
                float v[4];
                v[0] = __uint_as_float(r[j + 0]);
                v[1] = __uint_as_float(r[j + 1]);
                v[2] = __uint_as_float(r[j + 2]);
                v[3] = __uint_as_float(r[j + 3]);
                if (EPI) {
                    const int n = n0 + cbase + j;
                    v[0] += bias[n + 0];
                    v[1] += bias[n + 1];
                    v[2] += bias[n + 2];
                    v[3] += bias[n + 3];
                    if (zero) { v[0] = 0.f; v[1] = 0.f; v[2] = 0.f; v[3] = 0.f; }
                }
                if (OUTH) {
                    __half* crow = (__half*)Cv + (size_t)m * ldc + n0;
                    uint2 hv;
                    pack4h(v, hv);
                    *(uint2*)(crow + cbase + j) = hv;
                } else {
                    float* crow = (float*)Cv + (size_t)m * ldc + n0;
                    float4 fv;
                    fv.x = v[0]; fv.y = v[1]; fv.z = v[2]; fv.w = v[3];
                    *(float4*)(crow + cbase + j) = fv;
                }
            }
        }
        TCGEN05_FENCE_BEFORE();
    };

    for (int t = 0; t < TM_TILES; ++t) {
        // drive tile t's MMAs (async; writes D[t&1])
        if (wid == 0 && elect_one_pred()) {
            if (!bwaited) {
                MBARRIER_WAIT_PARITY(smem_u32(&s_bfull), 0);
                bwaited = 1;
            }
            const uint32_t D = tmem_base + ((t & 1) << 7);
            for (int c = 0; c < NCHUNKS; ++c) {
                const int g = t * NCHUNKS + c;
                const int st = g % A_NSTAGES;
                MBARRIER_WAIT_PARITY(smem_u32(&s_full[st]), fph[st]);
                fph[st] ^= 1;

                const uint64_t dA = MAKE_SMEM_DESC(aBase + st * A_STAGE_BYTES);
                const uint64_t dB = MAKE_SMEM_DESC(sbase + c * TILE_BYTES);
#pragma unroll
                for (int s = 0; s < 4; ++s) {
                    const bool first = (c == 0) && (s == 0);
                    mma_f16_ss(D, dA + 2 * s, dB + 2 * s, MMA_IDESC, !first);
                }
                if (g + A_NSTAGES < gmax) {
                    TCGEN05_COMMIT(smem_u32(&s_empty[st]));
                    MBARRIER_WAIT_PARITY(smem_u32(&s_empty[st]), eph[st]);
                    eph[st] ^= 1;
                    const uint32_t fb = smem_u32(&s_full[st]);
                    MBARRIER_EXPECT_TX(fb, A_STAGE_BYTES);
                    cp_bulk(aBase + st * A_STAGE_BYTES,
                            pAbase + (size_t)(g + A_NSTAGES) * TILE_BYTES,
                            A_STAGE_BYTES, fb);
                }
            }
            TCGEN05_COMMIT(smem_u32(&s_done[t & 1]));
        }
        // epilogue of previous tile (overlaps tile t's MMAs)
        if (t >= 1) {
            const int pt = t - 1;
            MBARRIER_WAIT_PARITY(smem_u32(&s_done[pt & 1]), dph[pt & 1]);
            dph[pt & 1] ^= 1;
            TCGEN05_FENCE_AFTER();
            epilogue(pt);
            __syncthreads();   // all warps done reading D[pt&1] before tile pt+2 rewrites it
        }
    }
    // final tile's epilogue
    {
        const int pt = TM_TILES - 1;
        MBARRIER_WAIT_PARITY(smem_u32(&s_done[pt & 1]), dph[pt & 1]);
        dph[pt & 1] ^= 1;
        TCGEN05_FENCE_AFTER();
        epilogue(pt);
    }

    __syncthreads();
    if (tid == 0) {
#pragma unroll
        for (int j = 0; j < A_NSTAGES; ++j) {
            MBARRIER_INVAL(smem_u32(&s_full[j]));
            MBARRIER_INVAL(smem_u32(&s_empty[j]));
        }
        MBARRIER_INVAL(smem_u32(&s_done[0]));
        MBARRIER_INVAL(smem_u32(&s_done[1]));
        MBARRIER_INVAL(smem_u32(&s_bfull));
    }
    __syncthreads();
    if (wid == 0) TCGEN05_DEALLOC(tmem_base, 256);

#else
    // ============== mma.sync fallback: B resident, per-tile A pipeline =======
    const int wm = (wid & 1) << 6;
    const int wn = (wid >> 1) << 5;

    // load B panel cooperatively (identity copy: layout pre-swizzled)
    {
#pragma unroll
        for (int i = 0; i < 32; ++i) {
            const uint32_t u = (tid + (i << 8)) << 4;   // 0..131056
            cp16(sbase + u, pBbase + u);
        }
        asm volatile("cp.async.commit_group;" ::: "memory");
        asm volatile("cp.async.wait_group 0;" ::: "memory");
        __syncthreads();
    }

    auto issue_A = [&](int g, int st) {
        const uint32_t sb = aBase + st * A_STAGE_BYTES;
        const char* pA = pAbase + (size_t)g * TILE_BYTES;
#pragma unroll
        for (int i = 0; i < 4; ++i) {
            const uint32_t u = (tid + (i << 8)) << 4;
            cp16(sb + u, pA + u);
        }
        asm volatile("cp.async.commit_group;" ::: "memory");
    };

    for (int t = 0; t < TM_TILES; ++t) {
        float acc[4][4][4];
#pragma unroll
        for (int a = 0; a < 4; ++a)
#pragma unroll
            for (int b = 0; b < 4; ++b)
#pragma unroll
                for (int d = 0; d < 4; ++d) acc[a][b][d] = 0.f;

        issue_A(t * NCHUNKS + 0, 0);
        issue_A(t * NCHUNKS + 1, 1);

        for (int c = 0; c < NCHUNKS; ++c) {
            if (c < NCHUNKS - 1) asm volatile("cp.async.wait_group 1;" ::: "memory");
            else                 asm volatile("cp.async.wait_group 0;" ::: "memory");
            __syncthreads();
            const uint32_t sa = aBase + (c & 1) * A_STAGE_BYTES;
            const uint32_t sbB = sbase + c * TILE_BYTES;

#pragma unroll
            for (int ks = 0; ks < 4; ++ks) {
                uint32_t av[4][4];
#pragma unroll
                for (int mf = 0; mf < 4; ++mf) {
                    const uint32_t row = wm + (mf << 4) + (lane & 15);
                    const uint32_t kp = (ks << 1) + (lane >> 4);
                    const uint32_t off = (row << 7) + (kp << 4);
                    const uint32_t sw = off ^ ((off >> 3) & 0x70);
                    ldsm4(av[mf], sa + sw);
                }
                uint32_t bv[4][2];
#pragma unroll
                for (int nb = 0; nb < 2; ++nb) {
                    const uint32_t row = wn + (nb << 4) + ((lane >> 4) << 3) + (lane & 7);
                    const uint32_t kp = (ks << 1) + ((lane >> 3) & 1);
                    const uint32_t off = (row << 7) + (kp << 4);
                    const uint32_t sw = off ^ ((off >> 3) & 0x70);
                    uint32_t tt[4];
                    ldsm4(tt, sbB + sw);
                    bv[2 * nb][0] = tt[0]; bv[2 * nb][1] = tt[1];
                    bv[2 * nb + 1][0] = tt[2]; bv[2 * nb + 1][1] = tt[3];
                }
#pragma unroll
                for (int mf = 0; mf < 4; ++mf)
#pragma unroll
                    for (int nf = 0; nf < 4; ++nf)
                        mma_fp16(acc[mf][nf], av[mf], bv[nf]);
            }
            __syncthreads();
            if (c + 2 < NCHUNKS) issue_A(t * NCHUNKS + c + 2, (c + 2) & 1);
        }

        const int m0 = (pm0 + t) << 7;
#pragma unroll
        for (int mf = 0; mf < 4; ++mf) {
#pragma unroll
            for (int half = 0; half < 2; ++half) {
                const int m = m0 + wm + (mf << 4) + (half << 3) + (lane >> 2);
                bool zero = false;
                if (EPI) zero = (post_mask[m] != 0);
#pragma unroll
                for (int nf = 0; nf < 4; ++nf) {
                    const int col = n0 + wn + (nf << 3) + ((lane & 3) << 1);
                    float v0 = acc[mf][nf][half * 2 + 0];
                    float v1 = acc[mf][nf][half * 2 + 1];
                    if (EPI) {
                        v0 += bias[col];
                        v1 += bias[col + 1];
                        if (zero) { v0 = 0.f; v1 = 0.f; }
                    }
                    if (OUTH) {
                        __half* crow = (__half*)Cv + (size_t)m * ldc;
                        __half2 h2;
                        h2.x = __float2half(v0);
                        h2.y = __float2half(v1);
                        *(__half2*)(crow + col) = h2;
                    } else {
                        float* crow = (float*)Cv + (size_t)m * ldc;
                        crow[col] = v0;
                        crow[col + 1] = v1;
                    }
                }
            }
        }
        __syncthreads();
    }
#endif
}

// ---------------------------------------------------------------------------
// Splits: fp32 -> fp16 into TILED+SWIZZLED layout.
// ---------------------------------------------------------------------------
__global__ void __launch_bounds__(256)
split_tiledA(const float* __restrict__ in, __half* __restrict__ hh,
             __half* __restrict__ qh, int Mtot, int withQ)
{
    int i = blockIdx.x * blockDim.x + threadIdx.x;
    const int units = Mtot << 6;
    if (i >= units) return;
    const int m = i >> 6;
    const int k = (i & 63) << 3;

    float x[8];
    const float* src = in + (size_t)m * GK + k;
#pragma unroll
    for (int j = 0; j < 8; ++j) x[j] = src[j];

    uint4 hv;
    pack8h(x, hv);

    const size_t o = tiled_off(m, k);
    *(uint4*)((char*)hh + o) = hv;

    if (withQ && (m & 255) < 64) {
        const int mq = ((m >> 8) << 6) + (m & 63);
        const size_t oq = tiled_off(mq, k);
        *(uint4*)((char*)qh + oq) = hv;
    }
}

__global__ void __launch_bounds__(256)
splitT_tiled(const float* __restrict__ in, __half* __restrict__ hT, int Nd)
{
    int i = blockIdx.x * blockDim.x + threadIdx.x;
    const int units = Nd << 6;
    if (i >= units) return;
    const int n = i >> 6;
    const int k = (i & 63) << 3;

    float x[8];
#pragma unroll
    for (int j = 0; j < 8; ++j) x[j] = in[(size_t)(k + j) * Nd + n];
    uint4 hv;
    pack8h(x, hv);

    const size_t o = tiled_off(n, k);
    *(uint4*)((char*)hT + o) = hv;
}

// ---------------------------------------------------------------------------
// Attention v4 (Round-15 proven): HMMA S and P@V; bitmask softmax.
// One CTA per (head, batch), 256 threads = 8 warps, 1 CTA/SM (184KB smem).
//
// smem (bytes):
//   sQ   fp16 [64][72]    @ 0        (9216)   - Q, pre-scaled by 1/8
//   sK   fp16 [256][72]   @ 9216     (36864)
//   sV   fp16 [256][72]   @ 46080    (36864)
//   sS   fp32 [64][260]   @ 82944    (66560)
//   sP   fp16 [64][264]   @ 149504   (33792)  - unnormalized exp weights
//   sRed fp32 [256]       @ 183296
//   sInv fp32 [64]        @ 184320
// ---------------------------------------------------------------------------
#define AT_QS 72
#define AT_KS 72
#define AT_SS 260
#define AT_PS 264
#define ATTN_SMEM_BYTES 184576

__global__ void __launch_bounds__(256)
attn_kernel(const __half* __restrict__ Q,
            const __half* __restrict__ KV,
            const int* __restrict__ pre_mask,
            __half* __restrict__ Ah)
{
    extern __shared__ char smem[];
    __half* sQ  = (__half*)(smem);
    __half* sK  = (__half*)(smem + 9216);
    __half* sV  = (__half*)(smem + 46080);
    float*  sS  = (float*)(smem + 82944);
    __half* sP  = (__half*)(smem + 149504);
    float*  sRed = (float*)(smem + 183296);
    float*  sInv = (float*)(smem + 184320);

    const int tid = threadIdx.x;
    const int wid = tid >> 5;
    const int lane = tid & 31;
    const int h = blockIdx.x;
    const int bs = blockIdx.y;
    const float NEG_INF = -INFINITY;

    // ---- load Q (scaled 1/8), K, V into padded fp16 smem ----
    {
        const __half2 hsc = __half2half2(__float2half(0.125f));
#pragma unroll
        for (int it = 0; it < 2; ++it) {
            const int u = tid + (it << 8);       // 0..511
            const int q = u >> 3, c = u & 7;
            uint4 v = *(const uint4*)(Q + ((size_t)(bs * NQ + q) << 9) + h * HEAD_DIM + (c << 3));
            __half2* hp = (__half2*)&v;
#pragma unroll
            for (int j = 0; j < 4; ++j) hp[j] = __hmul2(hp[j], hsc);
            *(uint4*)(sQ + q * AT_QS + (c << 3)) = v;
        }
#pragma unroll
        for (int it = 0; it < 8; ++it) {
            const int u = tid + (it << 8);       // 0..2047
            const int e = u >> 3, c = u & 7;
            const size_t base = ((size_t)(bs * NE + e) << 10) + h * HEAD_DIM + (c << 3);
            *(uint4*)(sK + e * AT_KS + (c << 3)) = *(const uint4*)(KV + base);
            *(uint4*)(sV + e * AT_KS + (c << 3)) = *(const uint4*)(KV + base + EMBED_DIM);
        }
    }
    __syncthreads();

    // ---- S = Qs @ K^T via mma: warp w -> entity cols [32w, 32w+32), all 64 q ----
    {
        const int n0w = wid << 5;
        float acc[4][4][4];
#pragma unroll
        for (int i = 0; i < 4; ++i)
#pragma unroll
            for (int j = 0; j < 4; ++j)
#pragma unroll
                for (int d = 0; d < 4; ++d) acc[i][j][d] = 0.f;

#pragma unroll
        for (int ks = 0; ks < 4; ++ks) {
            uint32_t a[4][4];
#pragma unroll
            for (int i = 0; i < 4; ++i) {
                const int row = (i << 4) + (lane & 15);
                const int col = (ks << 4) + ((lane >> 4) << 3);
                ldsm4(a[i], smem_u32(sQ + row * AT_QS + col));
            }
            uint32_t b[4][2];
#pragma unroll
            for (int nb = 0; nb < 2; ++nb) {
                const int row = n0w + (nb << 4) + ((lane >> 4) << 3) + (lane & 7);
                const int col = (ks << 4) + (((lane >> 3) & 1) << 3);
                uint32_t t[4];
                ldsm4(t, smem_u32(sK + row * AT_KS + col));
                b[2 * nb][0] = t[0]; b[2 * nb][1] = t[1];
                b[2 * nb + 1][0] = t[2]; b[2 * nb + 1][1] = t[3];
            }
#pragma unroll
            for (int i = 0; i < 4; ++i)
#pragma unroll
                for (int j = 0; j < 4; ++j)
                    mma_fp16(acc[i][j], a[i], b[j]);
        }
        const int g = lane >> 2;
        const int t2 = (lane & 3) << 1;
#pragma unroll
        for (int i = 0; i < 4; ++i) {
#pragma unroll
            for (int j = 0; j < 4; ++j) {
                const int q = (i << 4) + g;
                const int k = n0w + (j << 3) + t2;
                float2 lo; lo.x = acc[i][j][0]; lo.y = acc[i][j][1];
                float2 hi; hi.x = acc[i][j][2]; hi.y = acc[i][j][3];
                *(float2*)&sS[q * AT_SS + k] = lo;
                *(float2*)&sS[(q + 8) * AT_SS + k] = hi;
            }
        }
    }
    __syncthreads();

    // ---- masked softmax (bitmask; interleaved float4 parts) ----
    {
        const int row = tid >> 2;
        const int part = tid & 3;

        const int4* mrow = (const int4*)(pre_mask + ((size_t)bs * NQ + row) * NE);
        uint64_t bits = 0;
#pragma unroll
        for (int it = 0; it < 16; ++it) {
            int4 m = mrow[(it << 2) + part];   // k = it*16 + part*4
            uint64_t b = (uint64_t)(m.x != 0) | ((uint64_t)(m.y != 0) << 1) |
                         ((uint64_t)(m.z != 0) << 2) | ((uint64_t)(m.w != 0) << 3);
            bits |= b << (it << 2);
        }

        float mx = NEG_INF;
#pragma unroll
        for (int it = 0; it < 16; ++it) {
            float4 v = *(const float4*)&sS[row * AT_SS + (it << 4) + (part << 2)];
            const uint32_t mb = (uint32_t)(bits >> (it << 2)) & 15u;
            if (!(mb & 1u)) mx = fmaxf(mx, v.x);
            if (!(mb & 2u)) mx = fmaxf(mx, v.y);
            if (!(mb & 4u)) mx = fmaxf(mx, v.z);
            if (!(mb & 8u)) mx = fmaxf(mx, v.w);
        }
        sRed[(row << 2) + part] = mx;
        __syncthreads();
        const float rm = fmaxf(fmaxf(sRed[row << 2], sRed[(row << 2) + 1]),
                               fmaxf(sRed[(row << 2) + 2], sRed[(row << 2) + 3]));
        __syncthreads();

        const bool live = (rm != NEG_INF);
        float ssum = 0.f;
#pragma unroll
        for (int it = 0; it < 16; ++it) {
            float4 v = *(const float4*)&sS[row * AT_SS + (it << 4) + (part << 2)];
            const uint32_t mb = (uint32_t)(bits >> (it << 2)) & 15u;
            float e0 = (live && !(mb & 1u)) ? __expf(v.x - rm) : 0.f;
            float e1 = (live && !(mb & 2u)) ? __expf(v.y - rm) : 0.f;
            float e2 = (live && !(mb & 4u)) ? __expf(v.z - rm) : 0.f;
            float e3 = (live && !(mb & 8u)) ? __expf(v.w - rm) : 0.f;
            ssum += (e0 + e1) + (e2 + e3);
            float ev[4] = {e0, e1, e2, e3};
            uint2 hv;
            pack4h(ev, hv);
            *(uint2*)(sP + row * AT_PS + (it << 4) + (part << 2)) = hv;
        }
        sRed[(row << 2) + part] = ssum;
        __syncthreads();
        if (tid < 64) {
            const float t = sRed[tid << 2] + sRed[(tid << 2) + 1] +
                            sRed[(tid << 2) + 2] + sRed[(tid << 2) + 3];
            sInv[tid] = (t > 0.f) ? (1.f / t) : 0.f;
        }
    }
    __syncthreads();

    // ---- out = P @ V via mma: warp w -> q rows [16*(w&3)), d cols [32*(w>>2)) ----
    {
        const int q0 = (wid & 3) << 4;
        const int d0 = (wid >> 2) << 5;
        float acc[4][4];
#pragma unroll
        for (int j = 0; j < 4; ++j)
#pragma unroll
            for (int d = 0; d < 4; ++d) acc[j][d] = 0.f;

#pragma unroll 4
        for (int ks = 0; ks < 16; ++ks) {
            const int e0 = ks << 4;
            uint32_t a[4];
            {
                const int row = q0 + (lane & 15);
                const int col = e0 + ((lane >> 4) << 3);
                ldsm4(a, smem_u32(sP + row * AT_PS + col));
            }
            uint32_t b[4][2];
#pragma unroll
            for (int nb = 0; nb < 2; ++nb) {
                const int row = e0 + (lane & 7) + (((lane >> 3) & 1) << 3);
                const int col = d0 + (nb << 4) + ((lane >> 4) << 3);
                uint32_t t[4];
                ldsm4t(t, smem_u32(sV + row * AT_KS + col));
                b[2 * nb][0] = t[0]; b[2 * nb][1] = t[1];
                b[2 * nb + 1][0] = t[2]; b[2 * nb + 1][1] = t[3];
            }
#pragma unroll
            for (int j = 0; j < 4; ++j)
                mma_fp16(acc[j], a, b[j]);
        }

        const int g = lane >> 2;
        const int t2 = (lane & 3) << 1;
        const float inv0 = sInv[q0 + g];
        const float inv1 = sInv[q0 + g + 8];
        const int m0r = bs * NQ + q0 + g;
#pragma unroll
        for (int j = 0; j < 4; ++j) {
            const int d = d0 + (j << 3) + t2;
            const int kk0 = (h * HEAD_DIM + d) & ~7;
            const int sub = ((h * HEAD_DIM + d) & 7) << 1;
            {
                __half2 h2;
                h2.x = __float2half(acc[j][0] * inv0);
                h2.y = __float2half(acc[j][1] * inv0);
                *(uint32_t*)((char*)Ah + tiled_off(m0r, kk0) + sub) = *(uint32_t*)&h2;
            }
            {
                __half2 h2;
                h2.x = __float2half(acc[j][2] * inv1);
                h2.y = __float2half(acc[j][3] * inv1);
                *(uint32_t*)((char*)Ah + tiled_off(m0r + 8, kk0) + sub) = *(uint32_t*)&h2;
            }
        }
    }
}

// ---------------------------------------------------------------------------
// kernel_launch
// ---------------------------------------------------------------------------
extern "C" void kernel_launch(void* const* d_in, const int* in_sizes, int n_in,
                              void* d_out, int out_size)
{
    const float* entities  = (const float*)d_in[0];
    const int*   pre_mask  = (const int*)d_in[1];
    const int*   post_mask = (const int*)d_in[2];
    const float* W_in      = (const float*)d_in[3];
    const float* W_out     = (const float*)d_in[4];
    const float* b_out     = (const float*)d_in[5];
    float* out = (float*)d_out;

    __half *Qs, *KVs;
    __half *eh, *qh, *ah, *wih, *woh;
    cudaGetSymbolAddress((void**)&Qs, g_Q);
    cudaGetSymbolAddress((void**)&KVs, g_KV);
    cudaGetSymbolAddress((void**)&eh, g_ent_h);
    cudaGetSymbolAddress((void**)&qh, g_q_h);
    cudaGetSymbolAddress((void**)&ah, g_attn_h);
    cudaGetSymbolAddress((void**)&wih, g_WinT_h);
    cudaGetSymbolAddress((void**)&woh, g_WoutT_h);

    cudaFuncSetAttribute((const void*)gemm_fp16<false, true>,
                         cudaFuncAttributeMaxDynamicSharedMemorySize, GEMM_DYN_SMEM);
    cudaFuncSetAttribute((const void*)gemm_fp16<true, false>,
                         cudaFuncAttributeMaxDynamicSharedMemorySize, GEMM_DYN_SMEM);
    cudaFuncSetAttribute(attn_kernel,
                         cudaFuncAttributeMaxDynamicSharedMemorySize, ATTN_SMEM_BYTES);

    // 1) split entities -> tiled fp16 (+ compact Q rows)
    {
        int units = (BS * NE) << 6;
        split_tiledA<<<(units + 255) / 256, 256>>>(entities, eh, qh, BS * NE, 1);
    }
    // 2) split+transpose weights -> tiled fp16
    {
        int u1 = QKV_DIM << 6;
        splitT_tiled<<<(u1 + 255) / 256, 256>>>(W_in, wih, QKV_DIM);
        int u2 = OUT_DIM << 6;
        splitT_tiled<<<(u2 + 255) / 256, 256>>>(W_out, woh, OUT_DIM);
    }
    // 3) Q = q_ent @ W_in[:, 0:512]   M=32768 (256 panels / 8 per CTA), N=512
    gemm_fp16<false, true><<<dim3(EMBED_DIM / 128, (BS * NQ / 128) / TM_TILES), 256, GEMM_DYN_SMEM>>>(
        qh, wih, Qs, EMBED_DIM, nullptr, nullptr);

    // 4) KV = entities @ W_in[:, 512:1536]  M=131072 (1024 panels / 8 per CTA), N=1024
    gemm_fp16<false, true><<<dim3((2 * EMBED_DIM) / 128, (BS * NE / 128) / TM_TILES), 256, GEMM_DYN_SMEM>>>(
        eh, wih + 262144, KVs, 2 * EMBED_DIM, nullptr, nullptr);

    // 5) attention (HMMA; fp16 in, writes tiled fp16 directly)
    attn_kernel<<<dim3(N_HEADS, BS), 256, ATTN_SMEM_BYTES>>>(Qs, KVs, pre_mask, ah);

    // 6) out = ATTN @ W_out + b_out, post-masked  (fp32 output)
    gemm_fp16<true, false><<<dim3(OUT_DIM / 128, (BS * NQ / 128) / TM_TILES), 256, GEMM_DYN_SMEM>>>(
        ah, woh, out, OUT_DIM, b_out, post_mask);
}